// round 13
// baseline (speedup 1.0000x reference)
#include <cuda_runtime.h>

#define Bsz   128
#define Tt    512
#define INs   27
#define G4    1024
#define OUTs  128

// ---- persistent device scratch (static: no runtime allocation) ----
__device__ float g_G[(size_t)Tt * G4 * Bsz];        // [t][g(1024)][b(128)]
// tagged-h ring: u64 = {h[2b+1] | h[2b]}, each fp32 carries step-tag in 2 LSBs.
// layout [slot(4)][grp(16)][k(256)][bpair(4)]
__device__ unsigned long long g_hx[4 * 16 * 256 * 4];

// ---------------- helpers ----------------
__device__ __forceinline__ void fma2(unsigned long long& d, unsigned long long a, unsigned long long b) {
    asm("fma.rn.f32x2 %0, %1, %2, %0;" : "+l"(d) : "l"(a), "l"(b));
}
__device__ __forceinline__ void add2(unsigned long long& d, unsigned long long a) {
    asm("add.rn.f32x2 %0, %0, %1;" : "+l"(d) : "l"(a));
}
__device__ __forceinline__ unsigned long long ldrx(const unsigned long long* p) {
    unsigned long long v;
    asm volatile("ld.relaxed.gpu.global.u64 %0, [%1];" : "=l"(v) : "l"(p) : "memory");
    return v;
}
__device__ __forceinline__ void strx(unsigned long long* p, unsigned long long v) {
    asm volatile("st.relaxed.gpu.global.u64 [%0], %1;" :: "l"(p), "l"(v) : "memory");
}
__device__ __forceinline__ float sigf(float x) {
    return __fdividef(1.f, 1.f + __expf(-x));
}
__device__ __forceinline__ float tanhf_(float x) {
    float e = __expf(-2.f * fabsf(x));
    float r = __fdividef(1.f - e, 1.f + e);
    return copysignf(r, x);
}

// ---------------- kernels ----------------
// G[t][g][b] = b_ih[g] + b_hh[g] + sum_{k<27} x[b][t][k] * W_ih[g][k]
// Also seed ring: slot 0 = h_0 = 0.0f (tag 0), slots 1..3 = tag-3 sentinel.
__global__ void pre_kernel(const float* __restrict__ x,
                           const float* __restrict__ W_ih,
                           const float* __restrict__ b_ih,
                           const float* __restrict__ b_hh) {
    __shared__ float xs[Bsz * INs];
    const int t   = blockIdx.x;
    const int gc  = blockIdx.y;       // 0..7, 128 gates each
    const int tid = threadIdx.x;      // = b  (blockDim.x == 128)

    if (gc == 0) {                    // 512*128 threads cover 65536 ring entries
        int e = t * 128 + tid;
        g_hx[e] = (e < 16384) ? 0ULL : 0x0000000300000003ULL;
    }

    for (int i = tid; i < Bsz * INs; i += 128) {
        int b = i / INs, k = i - b * INs;
        xs[i] = x[((size_t)b * Tt + t) * INs + k];
    }
    __syncthreads();
    float xr[INs];
    #pragma unroll
    for (int k = 0; k < INs; ++k) xr[k] = xs[tid * INs + k];

    for (int g0 = 0; g0 < 128; ++g0) {
        int g = (gc << 7) + g0;
        float acc = b_ih[g] + b_hh[g];
        const float* wr = W_ih + g * 47;   // NN_IN = 47, only first 27 cols used
        #pragma unroll
        for (int k = 0; k < INs; ++k) acc += xr[k] * __ldg(wr + k);
        g_G[((size_t)t * G4 + g) * Bsz + tid] = acc;
    }
}

// Persistent sequential LSTM. 256 blocks = 16 batch-groups(8 batches) x 16 j-tiles(16 j).
// 256 threads = 8 warps. Warp = k-split ks(0..7, 32 k); lane = (gh, jl);
// thread = gates {2gh,2gh+1} of column j0+jl: w[2][32] in regs. 2 blocks/SM co-resident.
__global__ void __launch_bounds__(256, 2)
step_kernel(const float* __restrict__ W_hh,
            const float* __restrict__ W_fc,
            const float* __restrict__ b_fc,
            float* __restrict__ out) {
    extern __shared__ unsigned long long smu[];
    unsigned long long* sHd = smu;              // 1024 u64: [ks(8)][klocal*4+bp]
    unsigned long long* sRd = smu + 1024;       // 2 bufs x 2048 u64: [ks(8)][bp(4)][row(64)]
    unsigned long long* sG  = smu + 5120;       // 256 u64: [epi tid(64)][q(4)]

    const int tid  = threadIdx.x;
    const int ks   = tid >> 5;                  // warp = k-split 0..7 (32 k each)
    const int lane = tid & 31;
    const int jl   = lane & 15;                 // j-local 0..15
    const int gh   = lane >> 4;                 // gate-half 0..1
    const int grp  = blockIdx.x >> 4;           // batch-group 0..15
    const int jt   = blockIdx.x & 15;           // j-tile 0..15
    const int b0   = grp * 8;
    const int j0   = jt * 16;

    // ---- W slice: 2 gate-rows x 32 k in registers for the whole kernel ----
    float w[2][32];
    #pragma unroll
    for (int qq = 0; qq < 2; ++qq) {
        const int q = gh * 2 + qq;
        const float* wp = W_hh + (q * 256 + j0 + jl) * 256 + ks * 32;
        #pragma unroll
        for (int kk = 0; kk < 32; ++kk) w[qq][kk] = wp[kk];
    }

    // epilogue mapping (first 64 threads = warps 0,1): ej = j-local, eb = bpair
    const bool epi = (tid < 64);
    const int ej = tid & 15;
    const int eb = tid >> 4;                    // 0..3
    unsigned sGa = 0;
    if (epi) {
        unsigned sbase;
        asm("{ .reg .u64 t; cvta.to.shared.u64 t, %1; cvt.u32.u64 %0, t; }"
            : "=r"(sbase) : "l"(sG));
        sGa = sbase + tid * 32;                 // 4 u64 = 32 B per epi thread
    }

    float c0 = 0.f, c1 = 0.f;                   // cell state in registers (epi threads)

    for (int s = 0; s < Tt; ++s) {
        // ---- issue G prefetch via cp.async (epi threads) ----
        if (epi) {
            #pragma unroll
            for (int q = 0; q < 4; ++q) {
                const float* gs = g_G + ((size_t)s * 1024 + q * 256 + j0 + ej) * 128
                                      + b0 + eb * 2;
                asm volatile("cp.async.ca.shared.global [%0], [%1], 8;"
                             :: "r"(sGa + q * 8), "l"(gs) : "memory");
            }
            asm volatile("cp.async.commit_group;" ::: "memory");
        }

        // ---- poll own h slice (4 u64/thread), warp-private staging ----
        {
            const unsigned long long* p0 =
                g_hx + (size_t)(s & 3) * 16384 + (size_t)grp * 1024 + ks * 128 + lane;
            const unsigned long long pat =
                (unsigned long long)((unsigned)(s >> 2) & 3u) * 0x0000000100000001ULL;
            unsigned long long v0 = ldrx(p0),      v1 = ldrx(p0 + 32);
            unsigned long long v2 = ldrx(p0 + 64), v3 = ldrx(p0 + 96);
            int spins = 0;
            while (((v0 & 0x0000000300000003ULL) != pat) ||
                   ((v1 & 0x0000000300000003ULL) != pat) ||
                   ((v2 & 0x0000000300000003ULL) != pat) ||
                   ((v3 & 0x0000000300000003ULL) != pat)) {
                if (++spins > 16) __nanosleep(40);
                if ((v0 & 0x0000000300000003ULL) != pat) v0 = ldrx(p0);
                if ((v1 & 0x0000000300000003ULL) != pat) v1 = ldrx(p0 + 32);
                if ((v2 & 0x0000000300000003ULL) != pat) v2 = ldrx(p0 + 64);
                if ((v3 & 0x0000000300000003ULL) != pat) v3 = ldrx(p0 + 96);
            }
            sHd[ks * 128 + lane]      = v0;
            sHd[ks * 128 + lane + 32] = v1;
            sHd[ks * 128 + lane + 64] = v2;
            sHd[ks * 128 + lane + 96] = v3;
        }
        __syncwarp();

        // ---- GEMM: 2 gate-rows x 4 bpairs x 32 k; h broadcast LDS, W in regs ----
        unsigned long long acc[2][4];
        #pragma unroll
        for (int qq = 0; qq < 2; ++qq)
            #pragma unroll
            for (int p = 0; p < 4; ++p) acc[qq][p] = 0ULL;

        #pragma unroll
        for (int kk = 0; kk < 32; ++kk) {
            const ulonglong2* hh = (const ulonglong2*)(sHd + ks * 128 + kk * 4);
            ulonglong2 hA = hh[0];              // bpairs 0,1 (broadcast)
            ulonglong2 hB = hh[1];              // bpairs 2,3
            unsigned long long wd0, wd1;
            asm("mov.b64 %0, {%1, %1};" : "=l"(wd0) : "f"(w[0][kk]));
            asm("mov.b64 %0, {%1, %1};" : "=l"(wd1) : "f"(w[1][kk]));
            fma2(acc[0][0], hA.x, wd0); fma2(acc[0][1], hA.y, wd0);
            fma2(acc[0][2], hB.x, wd0); fma2(acc[0][3], hB.y, wd0);
            fma2(acc[1][0], hA.x, wd1); fma2(acc[1][1], hA.y, wd1);
            fma2(acc[1][2], hB.x, wd1); fma2(acc[1][3], hB.y, wd1);
        }

        // ---- partials: sR[buf][ks][bp][row = q*16 + jl] ----
        {
            unsigned long long* sRb = sRd + (s & 1) * 2048;
            #pragma unroll
            for (int qq = 0; qq < 2; ++qq)
                #pragma unroll
                for (int p = 0; p < 4; ++p)
                    sRb[ks * 256 + p * 64 + (gh * 2 + qq) * 16 + jl] = acc[qq][p];
        }
        __syncthreads();                        // the only block sync per step

        // ---- epilogue: sum 8 k-splits per gate, add G, LSTM, publish ----
        if (epi) {
            asm volatile("cp.async.wait_group 0;" ::: "memory");
            const unsigned long long* sRb = sRd + (s & 1) * 2048;
            unsigned long long vi = sG[tid * 4 + 0];
            unsigned long long vf = sG[tid * 4 + 1];
            unsigned long long vg = sG[tid * 4 + 2];
            unsigned long long vo = sG[tid * 4 + 3];
            const unsigned long long* rr = sRb + eb * 64 + ej;
            #pragma unroll
            for (int k2 = 0; k2 < 8; ++k2) {
                add2(vi, rr[0]);
                add2(vf, rr[16]);
                add2(vg, rr[32]);
                add2(vo, rr[48]);
                rr += 256;
            }
            float iL, iH, fL, fH, gL, gH, oL, oH;
            asm("mov.b64 {%0, %1}, %2;" : "=f"(iL), "=f"(iH) : "l"(vi));
            asm("mov.b64 {%0, %1}, %2;" : "=f"(fL), "=f"(fH) : "l"(vf));
            asm("mov.b64 {%0, %1}, %2;" : "=f"(gL), "=f"(gH) : "l"(vg));
            asm("mov.b64 {%0, %1}, %2;" : "=f"(oL), "=f"(oH) : "l"(vo));
            c0 = sigf(fL) * c0 + sigf(iL) * tanhf_(gL);
            c1 = sigf(fH) * c1 + sigf(iH) * tanhf_(gH);
            float h0 = sigf(oL) * tanhf_(c0);
            float h1 = sigf(oH) * tanhf_(c1);
            unsigned tagv = ((unsigned)(s + 1) >> 2) & 3u;
            unsigned u0 = (__float_as_uint(h0) & ~3u) | tagv;
            unsigned u1 = (__float_as_uint(h1) & ~3u) | tagv;
            unsigned long long pkt = (unsigned long long)u0 | ((unsigned long long)u1 << 32);
            strx(g_hx + (size_t)((s + 1) & 3) * 16384 + (size_t)grp * 1024
                      + (j0 + ej) * 4 + eb, pkt);
        }
        // no trailing sync: sR buffer parity protects the reduce; polls gate staging
    }

    // ---- classifier head: MUST read the block's OWN group (self-synchronized).
    // Blocks with jt<8 handle batch bb = grp*8 + jt. Reading another group is
    // unsafe: tag period is 16, unbounded cross-group skew can alias h_496 as h_512.
    if ((blockIdx.x & 15) < 8) {
        float* sHf = (float*)smu;
        const int bl = blockIdx.x & 7;          // batch within own group
        const int bb = grp * 8 + bl;            // global batch
        {
            const unsigned long long* p =
                g_hx + (size_t)grp * 1024 + tid * 4 + (bl >> 1);
            const unsigned sh = (bl & 1) * 32;
            unsigned long long v = ldrx(p);
            while ((unsigned)((v >> sh) & 3ULL) != 0u) { __nanosleep(40); v = ldrx(p); }
            sHf[tid] = __uint_as_float((unsigned)(v >> sh));
        }
        __syncthreads();
        if (tid < OUTs) {
            float acc = b_fc[tid];
            const float* wr = W_fc + tid * 256;
            #pragma unroll 8
            for (int k = 0; k < 256; ++k)
                acc += sHf[k] * wr[k];
            out[bb * OUTs + tid] = acc;
        }
    }
}

// ---------------- launcher ----------------
extern "C" void kernel_launch(void* const* d_in, const int* in_sizes, int n_in,
                              void* d_out, int out_size) {
    const float* x    = (const float*)d_in[0];
    // d_in[1] = input_lengths (unused by the reference)
    const float* W_ih = (const float*)d_in[2];
    const float* W_hh = (const float*)d_in[3];
    const float* b_ih = (const float*)d_in[4];
    const float* b_hh = (const float*)d_in[5];
    // d_in[6], d_in[7] = W_xi, b_xi — dead code (memory never affects output)
    const float* W_fc = (const float*)d_in[8];
    const float* b_fc = (const float*)d_in[9];
    float* out = (float*)d_out;

    // smem/block: (1024 + 4096 + 256) u64 = 5376 u64 = 43008 bytes; 2 blocks/SM = 86KB
    cudaFuncSetAttribute(step_kernel, cudaFuncAttributeMaxDynamicSharedMemorySize, 43008);

    pre_kernel<<<dim3(Tt, 8), 128>>>(x, W_ih, b_ih, b_hh);
    step_kernel<<<256, 256, 43008>>>(W_hh, W_fc, b_fc, out);
}

// round 15
// speedup vs baseline: 1.6218x; 1.6218x over previous
#include <cuda_runtime.h>

#define Bsz   128
#define Tt    512
#define INs   27
#define G4    1024
#define NB    128
#define OUTs  128

// ---- persistent device scratch (static: no runtime allocation) ----
__device__ float g_G[(size_t)Tt * G4 * Bsz];        // [t][g(1024)][b(128)]
// tagged-h ring: u64 = {h[2b+1] | h[2b]}, each fp32 carries step-tag in 2 LSBs.
// layout [slot(4)][grp(16)][k(256)][bpair(4)]
__device__ unsigned long long g_hx[4 * 16 * 256 * 4];

// ---------------- helpers ----------------
__device__ __forceinline__ void fma2(unsigned long long& d, unsigned long long a, unsigned long long b) {
    asm("fma.rn.f32x2 %0, %1, %2, %0;" : "+l"(d) : "l"(a), "l"(b));
}
__device__ __forceinline__ void add2(unsigned long long& d, unsigned long long a) {
    asm("add.rn.f32x2 %0, %0, %1;" : "+l"(d) : "l"(a));
}
__device__ __forceinline__ unsigned long long ldrx(const unsigned long long* p) {
    unsigned long long v;
    asm volatile("ld.relaxed.gpu.global.u64 %0, [%1];" : "=l"(v) : "l"(p) : "memory");
    return v;
}
__device__ __forceinline__ void strx(unsigned long long* p, unsigned long long v) {
    asm volatile("st.relaxed.gpu.global.u64 [%0], %1;" :: "l"(p), "l"(v) : "memory");
}
__device__ __forceinline__ float sigf(float x) {
    return __fdividef(1.f, 1.f + __expf(-x));
}
__device__ __forceinline__ float tanhf_(float x) {
    float e = __expf(-2.f * fabsf(x));
    float r = __fdividef(1.f - e, 1.f + e);
    return copysignf(r, x);
}

// ---------------- kernels ----------------
// G[t][g][b] = b_ih[g] + b_hh[g] + sum_{k<27} x[b][t][k] * W_ih[g][k]
// Also seed ring: slot 0 = h_0 = 0.0f (tag 0), slots 1..3 = tag-3 sentinel.
__global__ void pre_kernel(const float* __restrict__ x,
                           const float* __restrict__ W_ih,
                           const float* __restrict__ b_ih,
                           const float* __restrict__ b_hh) {
    __shared__ float xs[Bsz * INs];
    const int t   = blockIdx.x;
    const int gc  = blockIdx.y;       // 0..7, 128 gates each
    const int tid = threadIdx.x;      // = b  (blockDim.x == 128)

    if (gc == 0) {                    // 512*128 threads cover 65536 ring entries
        int e = t * 128 + tid;
        g_hx[e] = (e < 16384) ? 0ULL : 0x0000000300000003ULL;
    }

    for (int i = tid; i < Bsz * INs; i += 128) {
        int b = i / INs, k = i - b * INs;
        xs[i] = x[((size_t)b * Tt + t) * INs + k];
    }
    __syncthreads();
    float xr[INs];
    #pragma unroll
    for (int k = 0; k < INs; ++k) xr[k] = xs[tid * INs + k];

    for (int g0 = 0; g0 < 128; ++g0) {
        int g = (gc << 7) + g0;
        float acc = b_ih[g] + b_hh[g];
        const float* wr = W_ih + g * 47;   // NN_IN = 47, only first 27 cols used
        #pragma unroll
        for (int k = 0; k < INs; ++k) acc += xr[k] * __ldg(wr + k);
        g_G[((size_t)t * G4 + g) * Bsz + tid] = acc;
    }
}

// Persistent sequential LSTM. 128 blocks = 16 batch-groups(8 batches) x 8 j-tiles(32 j).
// Warp = k-split ks(0..15), 16 k each; lane = j-local; thread = all 4 gates of its j.
// Producer/consumer barrier, PARITY-ALTERNATED (ids 1,2): GEMM-only warps arrive and
// dive into the next poll; epi warps sync + reduce + publish. Two barriers prevent
// cross-step arrival mixing (step s and s+1 use different ids; s and s+2 can't overlap
// because h_{s+2} publication transitively requires this block's sync(s) to have fired).
__global__ void __launch_bounds__(512, 1)
step_kernel(const float* __restrict__ W_hh,
            const float* __restrict__ W_fc,
            const float* __restrict__ b_fc,
            float* __restrict__ out) {
    extern __shared__ unsigned long long smu[];
    unsigned long long* sHd = smu;              // 1024 u64: [ks(16)][kl*4+bp]
    unsigned long long* sRd = smu + 1024;       // 2 bufs x 8192 u64: [ks][q][bp][j]
    unsigned long long* sG  = smu + 1024 + 16384;  // 512 u64: [epi tid(128)][q(4)]

    const int tid  = threadIdx.x;
    const int ks   = tid >> 5;                  // warp = k-split 0..15
    const int lane = tid & 31;                  // j-local
    const int grp  = blockIdx.x >> 3;           // batch-group 0..15
    const int jt   = blockIdx.x & 7;            // j-tile 0..7
    const int b0   = grp << 3;
    const int j0   = jt << 5;

    // ---- W slice: 4 gate-rows x 16 k in registers for the whole kernel ----
    float w[4][16];
    #pragma unroll
    for (int q = 0; q < 4; ++q) {
        const float* wp = W_hh + (((q << 8) + j0 + lane) << 8) + (ks << 4);
        #pragma unroll
        for (int kk = 0; kk < 16; ++kk) w[q][kk] = wp[kk];
    }

    // epilogue mapping (first 128 threads): warp = bpair, lane = j-local
    const bool epi = (tid < 128);
    const int ej = tid & 31;                    // j-local
    const int eb = tid >> 5;                    // bpair 0..3
    unsigned sGa = 0;
    if (epi) {
        unsigned sbase;
        asm("{ .reg .u64 t; cvta.to.shared.u64 t, %1; cvt.u32.u64 %0, t; }"
            : "=r"(sbase) : "l"(sG));
        sGa = sbase + (tid << 5);               // 4 u64 = 32 B per epi thread
    }

    float c0 = 0.f, c1 = 0.f;                   // cell state in registers

    for (int s = 0; s < Tt; ++s) {
        // ---- issue G prefetch via cp.async (epi threads) ----
        if (epi) {
            #pragma unroll
            for (int q = 0; q < 4; ++q) {
                const float* gs = g_G + ((((size_t)s << 10) + (q << 8) + j0 + ej) << 7)
                                      + b0 + (eb << 1);
                asm volatile("cp.async.ca.shared.global [%0], [%1], 8;"
                             :: "r"(sGa + (q << 3)), "l"(gs) : "memory");
            }
            asm volatile("cp.async.commit_group;" ::: "memory");
        }

        // ---- poll own h slice (2 u64/thread), warp-private staging ----
        {
            const unsigned long long* p0 =
                g_hx + (((size_t)(s & 3)) << 14) + ((size_t)grp << 10) + (ks << 6) + lane;
            const unsigned long long pat =
                (unsigned long long)((unsigned)(s >> 2) & 3u) * 0x0000000100000001ULL;
            unsigned long long v0 = ldrx(p0), v1 = ldrx(p0 + 32);
            int spins = 0;
            while (((v0 & 0x0000000300000003ULL) != pat) ||
                   ((v1 & 0x0000000300000003ULL) != pat)) {
                if (++spins > 8) __nanosleep(40);
                if ((v0 & 0x0000000300000003ULL) != pat) v0 = ldrx(p0);
                if ((v1 & 0x0000000300000003ULL) != pat) v1 = ldrx(p0 + 32);
            }
            sHd[(ks << 6) + lane]      = v0;
            sHd[(ks << 6) + lane + 32] = v1;
        }
        __syncwarp();

        // ---- GEMM: 4 gate-rows x 4 bpairs x 16 k; h broadcast LDS, W in regs ----
        unsigned long long acc[4][4];
        #pragma unroll
        for (int q = 0; q < 4; ++q)
            #pragma unroll
            for (int p = 0; p < 4; ++p) acc[q][p] = 0ULL;

        #pragma unroll
        for (int kk = 0; kk < 16; ++kk) {
            const ulonglong2* hh = (const ulonglong2*)(sHd + (ks << 6) + (kk << 2));
            ulonglong2 hA = hh[0];              // bpairs 0,1 (broadcast)
            ulonglong2 hB = hh[1];              // bpairs 2,3
            #pragma unroll
            for (int q = 0; q < 4; ++q) {
                unsigned long long wd;
                asm("mov.b64 %0, {%1, %1};" : "=l"(wd) : "f"(w[q][kk]));
                fma2(acc[q][0], hA.x, wd); fma2(acc[q][1], hA.y, wd);
                fma2(acc[q][2], hB.x, wd); fma2(acc[q][3], hB.y, wd);
            }
        }

        // ---- partials: sR[buf][ks][q][bp][j(32)] ----
        {
            unsigned long long* sRb = sRd + ((s & 1) << 13);
            #pragma unroll
            for (int q = 0; q < 4; ++q)
                #pragma unroll
                for (int p = 0; p < 4; ++p)
                    sRb[(((ks << 2) + q) << 7) + (p << 5) + lane] = acc[q][p];
        }

        // ---- parity-alternated producer/consumer barrier ----
        const int barid = 1 + (s & 1);
        if (!epi) {
            asm volatile("bar.arrive %0, 512;" :: "r"(barid) : "memory");
            // fall through to the next step's poll — gated by other blocks'
            // publishes, not this block's epilogue.
        } else {
            asm volatile("bar.sync %0, 512;" :: "r"(barid) : "memory");

            // ---- epilogue: sum 16 k-splits per gate, add G, LSTM, publish ----
            asm volatile("cp.async.wait_group 0;" ::: "memory");
            const unsigned long long* sRb = sRd + ((s & 1) << 13);
            unsigned long long vi = sG[(tid << 2) + 0];
            unsigned long long vf = sG[(tid << 2) + 1];
            unsigned long long vg = sG[(tid << 2) + 2];
            unsigned long long vo = sG[(tid << 2) + 3];
            const unsigned long long* rr = sRb + (eb << 5) + ej;
            #pragma unroll
            for (int k2 = 0; k2 < 16; ++k2) {
                add2(vi, rr[0]);
                add2(vf, rr[128]);
                add2(vg, rr[256]);
                add2(vo, rr[384]);
                rr += 512;
            }
            float iL, iH, fL, fH, gL, gH, oL, oH;
            asm("mov.b64 {%0, %1}, %2;" : "=f"(iL), "=f"(iH) : "l"(vi));
            asm("mov.b64 {%0, %1}, %2;" : "=f"(fL), "=f"(fH) : "l"(vf));
            asm("mov.b64 {%0, %1}, %2;" : "=f"(gL), "=f"(gH) : "l"(vg));
            asm("mov.b64 {%0, %1}, %2;" : "=f"(oL), "=f"(oH) : "l"(vo));
            c0 = sigf(fL) * c0 + sigf(iL) * tanhf_(gL);
            c1 = sigf(fH) * c1 + sigf(iH) * tanhf_(gH);
            float h0 = sigf(oL) * tanhf_(c0);
            float h1 = sigf(oH) * tanhf_(c1);
            unsigned tagv = ((unsigned)(s + 1) >> 2) & 3u;
            unsigned u0 = (__float_as_uint(h0) & ~3u) | tagv;
            unsigned u1 = (__float_as_uint(h1) & ~3u) | tagv;
            unsigned long long pkt = (unsigned long long)u0 | ((unsigned long long)u1 << 32);
            strx(g_hx + (((size_t)((s + 1) & 3)) << 14) + ((size_t)grp << 10)
                      + ((j0 + ej) << 2) + eb, pkt);
        }
        // sR buffer parity: GEMM(s+2) stores (buffer s&1) gated by poll(h_{s+2})
        // -> epi(s+1) done -> epi(s) done reading buffer s&1. ✓
    }

    // ---- classifier head: poll h_T (slot 0, tag 0) for this block's batch ----
    // bb>>3 == this block's own grp (self-synchronized; no cross-group aliasing).
    {
        float* sHf = (float*)smu;
        const int bb = blockIdx.x;               // batch = block id
        if (tid < 256) {
            const unsigned long long* p =
                g_hx + (((size_t)(bb >> 3)) << 10) + (tid << 2) + ((bb & 7) >> 1);
            const unsigned sh = (bb & 1) << 5;
            unsigned long long v = ldrx(p);
            while ((unsigned)((v >> sh) & 3ULL) != 0u) { __nanosleep(40); v = ldrx(p); }
            sHf[tid] = __uint_as_float((unsigned)(v >> sh));
        }
        __syncthreads();
        if (tid < OUTs) {
            float acc = b_fc[tid];
            const float* wr = W_fc + tid * 256;
            #pragma unroll 8
            for (int k = 0; k < 256; ++k)
                acc += sHf[k] * wr[k];
            out[bb * OUTs + tid] = acc;
        }
    }
}

// ---------------- launcher ----------------
extern "C" void kernel_launch(void* const* d_in, const int* in_sizes, int n_in,
                              void* d_out, int out_size) {
    const float* x    = (const float*)d_in[0];
    // d_in[1] = input_lengths (unused by the reference)
    const float* W_ih = (const float*)d_in[2];
    const float* W_hh = (const float*)d_in[3];
    const float* b_ih = (const float*)d_in[4];
    const float* b_hh = (const float*)d_in[5];
    // d_in[6], d_in[7] = W_xi, b_xi — dead code (memory never affects output)
    const float* W_fc = (const float*)d_in[8];
    const float* b_fc = (const float*)d_in[9];
    float* out = (float*)d_out;

    // smem: 8KB (sHd) + 128KB (sRd double buffer) + 4KB (sG) = 143360 bytes
    cudaFuncSetAttribute(step_kernel, cudaFuncAttributeMaxDynamicSharedMemorySize, 143360);

    pre_kernel<<<dim3(Tt, 8), 128>>>(x, W_ih, b_ih, b_hh);
    step_kernel<<<NB, 512, 143360>>>(W_hh, W_fc, b_fc, out);
}